// round 1
// baseline (speedup 1.0000x reference)
#include <cuda_runtime.h>

#define BB 4
#define LL 512
#define DD 768
#define DOUT 384
#define KSEL 51
#define NROW (BB*LL)
#define NSPLIT 16

// ---- device scratch (static allocation; no cudaMalloc allowed) ----
__device__ float g_fsrc[NROW * DD];   // hidden @ W_src + b_src
__device__ float g_fdst[NROW * DD];   // hidden @ W_dst + b_dst
__device__ float g_h[NROW * DD];      // post-GAT hidden
__device__ int   g_idx[NROW * KSEL];  // top-K indices per (b,l)
__device__ float g_gate[NROW];        // gate logits -> softmax probs
__device__ float g_part[BB * NSPLIT * DD]; // partial pooled sums

// ============================================================
// 1) Top-K via rank counting. One block per row (b,l), 512 thr.
//    rank(i) = #{j: a[j]>a[i]} + #{j<i: a[j]==a[i]}  (matches top_k order)
// ============================================================
__global__ void topk_kernel(const float* __restrict__ attn) {
    __shared__ float s[LL];
    int row = blockIdx.x;
    int t = threadIdx.x;
    float v = attn[row * LL + t];
    s[t] = v;
    __syncthreads();
    int rank = 0;
#pragma unroll 8
    for (int j = 0; j < LL; j++) {
        float u = s[j];
        rank += (int)((u > v) || (u == v && j < t));
    }
    if (rank < KSEL) g_idx[row * KSEL + rank] = t;
}

// ============================================================
// 2) Fused GEMM: C[2048,1536] = hidden[2048,768] @ [W_src | W_dst] + bias
//    BM=128, BN=64, BK=16, 256 threads, 8x4 microtile.
// ============================================================
__global__ __launch_bounds__(256) void gemm_kernel(
    const float* __restrict__ A,
    const float* __restrict__ Wsrc, const float* __restrict__ bsrc,
    const float* __restrict__ Wdst, const float* __restrict__ bdst) {
    const int BM = 128, BN = 64, BK = 16;
    __shared__ float sA[BK][BM];
    __shared__ float sB[BK][BN];

    int tid = threadIdx.x;
    int colBase = blockIdx.x * BN;   // 0..1472
    int rowBase = blockIdx.y * BM;   // 0..1920

    const float* W;
    const float* bias;
    float* Cout;
    int cb;
    if (colBase < DD) { W = Wsrc; bias = bsrc; Cout = g_fsrc; cb = colBase; }
    else              { W = Wdst; bias = bdst; Cout = g_fdst; cb = colBase - DD; }

    int tx = tid & 15;       // 0..15 -> col group (4 cols)
    int ty = tid >> 4;       // 0..15 -> row group (8 rows)

    float acc[8][4];
#pragma unroll
    for (int i = 0; i < 8; i++)
#pragma unroll
        for (int j = 0; j < 4; j++) acc[i][j] = 0.f;

    int bRow = tid >> 4;          // 0..15
    int bCol = (tid & 15) * 4;    // 0..60

    for (int k0 = 0; k0 < DD; k0 += BK) {
        // load A tile 128x16 (2 x float4 per thread), transpose into sA[k][row]
#pragma unroll
        for (int q = 0; q < 2; q++) {
            int i4 = tid + q * 256;
            int r  = i4 >> 2;
            int kc = (i4 & 3) * 4;
            float4 a = *(const float4*)&A[(size_t)(rowBase + r) * DD + k0 + kc];
            sA[kc + 0][r] = a.x; sA[kc + 1][r] = a.y;
            sA[kc + 2][r] = a.z; sA[kc + 3][r] = a.w;
        }
        // load B tile 16x64 (1 x float4 per thread)
        float4 bq = *(const float4*)&W[(size_t)(k0 + bRow) * DD + cb + bCol];
        *(float4*)&sB[bRow][bCol] = bq;
        __syncthreads();

#pragma unroll
        for (int kk = 0; kk < BK; kk++) {
            float ra[8], rb[4];
#pragma unroll
            for (int i = 0; i < 8; i++) ra[i] = sA[kk][ty * 8 + i];
#pragma unroll
            for (int j = 0; j < 4; j++) rb[j] = sB[kk][tx * 4 + j];
#pragma unroll
            for (int i = 0; i < 8; i++)
#pragma unroll
                for (int j = 0; j < 4; j++) acc[i][j] += ra[i] * rb[j];
        }
        __syncthreads();
    }

#pragma unroll
    for (int i = 0; i < 8; i++) {
        int gr = rowBase + ty * 8 + i;
#pragma unroll
        for (int j = 0; j < 4; j++) {
            int gc = cb + tx * 4 + j;
            Cout[(size_t)gr * DD + gc] = acc[i][j] + bias[gc];
        }
    }
}

// ============================================================
// 3) Edge scores + softmax + aggregation + gate logit.
//    One block (256 thr) per (b,l).
// ============================================================
__global__ __launch_bounds__(256) void edge_kernel(
    const float* __restrict__ attn, const float* __restrict__ hidden,
    const float* __restrict__ attn_vec, const float* __restrict__ gat_bias,
    const float* __restrict__ gate_W, const float* __restrict__ gate_b) {
    __shared__ float fdst[DD];
    __shared__ float av[DD];
    __shared__ float wk[KSEL];
    __shared__ int   ik[KSEL];
    __shared__ float red[256];

    int row = blockIdx.x;
    int b = row / LL;
    int t = threadIdx.x;

    for (int d = t; d < DD; d += 256) {
        fdst[d] = g_fdst[(size_t)row * DD + d];
        av[d]   = attn_vec[d];
    }
    if (t < KSEL) ik[t] = g_idx[row * KSEL + t];
    __syncthreads();

    int warp = t >> 5, lane = t & 31;
    // scores: warps strided over k
    for (int k = warp; k < KSEL; k += 8) {
        int idxk = ik[k];
        const float* fs = &g_fsrc[(size_t)(b * LL + idxk) * DD];
        float sum = 0.f;
#pragma unroll 4
        for (int d = lane; d < DD; d += 32) {
            float x = fs[d] + fdst[d];
            x = x > 0.f ? x : 0.2f * x;
            sum += x * av[d];
        }
#pragma unroll
        for (int o = 16; o > 0; o >>= 1) sum += __shfl_xor_sync(0xffffffffu, sum, o);
        if (lane == 0) {
            float val = attn[(size_t)row * LL + idxk];
            wk[k] = (val > 0.f) ? sum : -1e9f;
        }
    }
    __syncthreads();

    // softmax over K (redundant per-thread, broadcast smem reads)
    float m = -1e30f;
    for (int k = 0; k < KSEL; k++) m = fmaxf(m, wk[k]);
    __syncthreads();
    if (t < KSEL) wk[t] = expf(wk[t] - m);
    __syncthreads();
    float Z = 0.f;
    for (int k = 0; k < KSEL; k++) Z += wk[k];
    float invZ = 1.f / Z;

    // aggregation: thread t owns d = t, t+256, t+512
    float a0 = 0.f, a1 = 0.f, a2 = 0.f;
    for (int k = 0; k < KSEL; k++) {
        const float* fs = &g_fsrc[(size_t)(b * LL + ik[k]) * DD];
        float w = wk[k] * invZ;
        a0 += w * fs[t];
        a1 += w * fs[t + 256];
        a2 += w * fs[t + 512];
    }

    float accv[3] = {a0, a1, a2};
    float gp = 0.f;
#pragma unroll
    for (int q = 0; q < 3; q++) {
        int d = t + q * 256;
        float x = accv[q] + hidden[(size_t)row * DD + d] + gat_bias[d];
        x = x > 0.f ? x : 0.01f * x;
        g_h[(size_t)row * DD + d] = x;
        gp += x * gate_W[d];
    }
    red[t] = gp;
    __syncthreads();
#pragma unroll
    for (int s = 128; s > 0; s >>= 1) {
        if (t < s) red[t] += red[t + s];
        __syncthreads();
    }
    if (t == 0) g_gate[row] = red[0] + gate_b[0];
}

// ============================================================
// 4) Gate softmax over L per batch. One block (512) per batch.
// ============================================================
__global__ void gatesm_kernel() {
    __shared__ float red[512];
    int b = blockIdx.x, t = threadIdx.x;
    float v = g_gate[b * LL + t];
    red[t] = v;
    __syncthreads();
#pragma unroll
    for (int s = 256; s > 0; s >>= 1) {
        if (t < s) red[t] = fmaxf(red[t], red[t + s]);
        __syncthreads();
    }
    float m = red[0];
    __syncthreads();
    float e = expf(v - m);
    red[t] = e;
    __syncthreads();
#pragma unroll
    for (int s = 256; s > 0; s >>= 1) {
        if (t < s) red[t] += red[t + s];
        __syncthreads();
    }
    float Z = red[0];
    g_gate[b * LL + t] = e / Z;
}

// ============================================================
// 5) Partial weighted pooling: grid (NSPLIT, B), 256 thr.
// ============================================================
__global__ void pool_kernel() {
    int b = blockIdx.y, s = blockIdx.x, t = threadIdx.x;
    float a0 = 0.f, a1 = 0.f, a2 = 0.f;
    int l0 = s * (LL / NSPLIT);
    for (int l = l0; l < l0 + (LL / NSPLIT); l++) {
        float p = g_gate[b * LL + l];
        const float* hr = &g_h[(size_t)(b * LL + l) * DD];
        a0 += p * hr[t];
        a1 += p * hr[t + 256];
        a2 += p * hr[t + 512];
    }
    float* o = &g_part[(size_t)(b * NSPLIT + s) * DD];
    o[t] = a0; o[t + 256] = a1; o[t + 512] = a2;
}

// ============================================================
// 6) Head: finish pool, relu, LN, FC(768->384), LN2. One block/batch, 384 thr.
// ============================================================
__device__ __forceinline__ float bsum(float v, float* red, int t, int n) {
    red[t] = v;
    __syncthreads();
#pragma unroll
    for (int s = 256; s > 0; s >>= 1) {
        if (t < s && t + s < n) red[t] += red[t + s];
        __syncthreads();
    }
    float r = red[0];
    __syncthreads();
    return r;
}

__global__ __launch_bounds__(DOUT) void head_kernel(
    const float* __restrict__ ln_g, const float* __restrict__ ln_b,
    const float* __restrict__ fc_W, const float* __restrict__ fc_b,
    const float* __restrict__ ln2_g, const float* __restrict__ ln2_b,
    float* __restrict__ out) {
    __shared__ float xn[DD];
    __shared__ float red[DOUT];
    int b = blockIdx.x, t = threadIdx.x;

    float x0 = 0.f, x1 = 0.f;
    for (int s = 0; s < NSPLIT; s++) {
        const float* pp = &g_part[(size_t)(b * NSPLIT + s) * DD];
        x0 += pp[t];
        x1 += pp[t + DOUT];
    }
    x0 = fmaxf(x0, 0.f);
    x1 = fmaxf(x1, 0.f);

    float mu  = bsum(x0 + x1, red, t, DOUT) * (1.f / DD);
    float q   = bsum(x0 * x0 + x1 * x1, red, t, DOUT) * (1.f / DD);
    float var = q - mu * mu;
    float rstd = rsqrtf(var + 1e-5f);
    xn[t]        = (x0 - mu) * rstd * ln_g[t] + ln_b[t];
    xn[t + DOUT] = (x1 - mu) * rstd * ln_g[t + DOUT] + ln_b[t + DOUT];
    __syncthreads();

    float o = fc_b[t];
#pragma unroll 4
    for (int d = 0; d < DD; d++) o += xn[d] * fc_W[d * DOUT + t];

    float mu2  = bsum(o, red, t, DOUT) * (1.f / DOUT);
    float q2   = bsum(o * o, red, t, DOUT) * (1.f / DOUT);
    float var2 = q2 - mu2 * mu2;
    out[b * DOUT + t] = (o - mu2) * rsqrtf(var2 + 1e-5f) * ln2_g[t] + ln2_b[t];
}

// ============================================================
extern "C" void kernel_launch(void* const* d_in, const int* in_sizes, int n_in,
                              void* d_out, int out_size) {
    const float* hidden = (const float*)d_in[0];
    const float* attn   = (const float*)d_in[1];
    const float* Wsrc   = (const float*)d_in[2];
    const float* bsrc   = (const float*)d_in[3];
    const float* Wdst   = (const float*)d_in[4];
    const float* bdst   = (const float*)d_in[5];
    const float* av     = (const float*)d_in[6];
    const float* gb     = (const float*)d_in[7];
    const float* gateW  = (const float*)d_in[8];
    const float* gateb  = (const float*)d_in[9];
    const float* lng    = (const float*)d_in[10];
    const float* lnb    = (const float*)d_in[11];
    const float* fcW    = (const float*)d_in[12];
    const float* fcb    = (const float*)d_in[13];
    const float* ln2g   = (const float*)d_in[14];
    const float* ln2b   = (const float*)d_in[15];
    float* out = (float*)d_out;

    topk_kernel<<<NROW, 512>>>(attn);
    gemm_kernel<<<dim3(24, 16), 256>>>(hidden, Wsrc, bsrc, Wdst, bdst);
    edge_kernel<<<NROW, 256>>>(attn, hidden, av, gb, gateW, gateb);
    gatesm_kernel<<<BB, 512>>>();
    pool_kernel<<<dim3(NSPLIT, BB), 256>>>();
    head_kernel<<<BB, DOUT>>>(lng, lnb, fcW, fcb, ln2g, ln2b, out);
}

// round 4
// speedup vs baseline: 1.8615x; 1.8615x over previous
#include <cuda_runtime.h>
#include <cstdint>

#define BB 4
#define LL 512
#define DD 768
#define DOUT 384
#define KSEL 51
#define NROW (BB*LL)
#define NSPLIT 16

// ---- device scratch (static allocation; no cudaMalloc allowed) ----
__device__ float g_fsrc[NROW * DD];   // hidden @ W_src + b_src
__device__ float g_fdst[NROW * DD];   // hidden @ W_dst + b_dst
__device__ float g_h[NROW * DD];      // post-GAT hidden
__device__ int   g_idx[NROW * KSEL];  // top-K indices per (b,l)
__device__ float g_gate[NROW];        // gate logits -> softmax probs
__device__ float g_part[BB * NSPLIT * DD]; // partial pooled sums

// ============================================================
// 1) Top-K via 4-round radix select on float bits (values >= 0).
//    One block per row, 512 threads. Selected SET matches top_k
//    exactly (ties broken by lowest index), order irrelevant
//    downstream (softmax + weighted sum are permutation invariant).
// ============================================================
__global__ __launch_bounds__(512) void topk_kernel(const float* __restrict__ attn) {
    __shared__ unsigned su[LL];
    __shared__ int hist[256];
    __shared__ int suf[256];
    __shared__ unsigned s_prefix;
    __shared__ int s_need;
    __shared__ int s_cnt;

    int row = blockIdx.x;
    int t = threadIdx.x;
    unsigned u = __float_as_uint(attn[(size_t)row * LL + t]); // all >= 0
    su[t] = u;
    if (t == 0) { s_prefix = 0u; s_need = KSEL; s_cnt = 0; }
    unsigned himask = 0u;
    __syncthreads();

#pragma unroll
    for (int shift = 24; shift >= 0; shift -= 8) {
        unsigned pref = s_prefix;
        int need = s_need;
        if (t < 256) hist[t] = 0;
        __syncthreads();

        bool cand = ((u & himask) == pref);
        if (cand) atomicAdd(&hist[(u >> shift) & 0xFF], 1);
        __syncthreads();

        if (t < 256) suf[t] = hist[t];
        __syncthreads();
        // suffix sum: suf[b] = # candidates with bin >= b
#pragma unroll
        for (int off = 1; off < 256; off <<= 1) {
            int add = 0;
            if (t < 256 && t + off < 256) add = suf[t + off];
            __syncthreads();
            if (t < 256) suf[t] += add;
            __syncthreads();
        }
        if (t < 256) {
            int above = (t + 1 < 256) ? suf[t + 1] : 0; // bins strictly greater
            if (suf[t] >= need && above < need) {       // unique t
                s_need = need - above;
                s_prefix = pref | ((unsigned)t << shift);
            }
        }
        himask |= (0xFFu << shift);
        __syncthreads();
    }

    unsigned T = s_prefix;   // exact bits of the K-th largest value
    int need = s_need;       // # elements equal to T to accept
    if (u > T) {
        int slot = atomicAdd(&s_cnt, 1);
        g_idx[row * KSEL + slot] = t;
    }
    __syncthreads();
    int ngt = s_cnt;         // == KSEL - need
    if (u == T) {
        int r = 0;
        for (int j = 0; j < t; j++) r += (su[j] == T);
        if (r < need) g_idx[row * KSEL + ngt + r] = t;
    }
}

// ============================================================
// 2) Fused tf32 tensor-core GEMM:
//    C[2048,1536] = hidden[2048,768] @ [W_src | W_dst] + bias
//    BM=128 BN=64 BK=32, 8 warps, mma.m16n8k8.tf32, reg-staged
//    double buffer, cvt.rna.tf32 on smem store.
// ============================================================
#define GBM 128
#define GBN 64
#define GBK 32

__device__ __forceinline__ float tf32r(float x) {
    float y;
    asm("cvt.rna.tf32.f32 %0, %1;" : "=f"(y) : "f"(x));
    return y;
}
__device__ __forceinline__ void mma_tf32(float* d, const uint32_t* a, const uint32_t* b) {
    asm volatile(
        "mma.sync.aligned.m16n8k8.row.col.f32.tf32.tf32.f32 "
        "{%0,%1,%2,%3}, {%4,%5,%6,%7}, {%8,%9}, {%0,%1,%2,%3};\n"
        : "+f"(d[0]), "+f"(d[1]), "+f"(d[2]), "+f"(d[3])
        : "r"(a[0]), "r"(a[1]), "r"(a[2]), "r"(a[3]), "r"(b[0]), "r"(b[1]));
}

__global__ __launch_bounds__(256) void gemm_tf32_kernel(
    const float* __restrict__ A,
    const float* __restrict__ Wsrc, const float* __restrict__ bsrc,
    const float* __restrict__ Wdst, const float* __restrict__ bdst) {
    __shared__ float sA[GBM][GBK + 4];  // row stride 36 floats (144B, 16B aligned)
    __shared__ float sB[GBK][GBN + 8];  // row stride 72 floats (288B, 16B aligned)

    int tid = threadIdx.x;
    int colBase = blockIdx.x * GBN;
    int rowBase = blockIdx.y * GBM;

    const float *W, *bias;
    float* Cout;
    int cb;
    if (colBase < DD) { W = Wsrc; bias = bsrc; Cout = g_fsrc; cb = colBase; }
    else              { W = Wdst; bias = bdst; Cout = g_fdst; cb = colBase - DD; }

    int lane = tid & 31, wid = tid >> 5;
    int warpM = wid & 3, warpN = wid >> 2;  // 4 x 2 warps, 32x32 each
    int g = lane >> 2, t4 = lane & 3;

    float acc[2][4][4];
#pragma unroll
    for (int i = 0; i < 2; i++)
#pragma unroll
        for (int j = 0; j < 4; j++)
#pragma unroll
            for (int q = 0; q < 4; q++) acc[i][j][q] = 0.f;

    float4 pa[4], pb[2];

    // prologue load (k0 = 0)
#pragma unroll
    for (int q = 0; q < 4; q++) {
        int i = tid + q * 256; int r = i >> 3; int c = i & 7;
        pa[q] = *(const float4*)&A[(size_t)(rowBase + r) * DD + c * 4];
    }
#pragma unroll
    for (int q = 0; q < 2; q++) {
        int i = tid + q * 256; int r = i >> 4; int c = i & 15;
        pb[q] = *(const float4*)&W[(size_t)r * DD + cb + c * 4];
    }

    for (int k0 = 0; k0 < DD; k0 += GBK) {
        // commit staged tile to smem (with tf32 rounding)
#pragma unroll
        for (int q = 0; q < 4; q++) {
            int i = tid + q * 256; int r = i >> 3; int c = i & 7;
            float4 v = pa[q];
            v.x = tf32r(v.x); v.y = tf32r(v.y); v.z = tf32r(v.z); v.w = tf32r(v.w);
            *(float4*)&sA[r][c * 4] = v;
        }
#pragma unroll
        for (int q = 0; q < 2; q++) {
            int i = tid + q * 256; int r = i >> 4; int c = i & 15;
            float4 v = pb[q];
            v.x = tf32r(v.x); v.y = tf32r(v.y); v.z = tf32r(v.z); v.w = tf32r(v.w);
            *(float4*)&sB[r][c * 4] = v;
        }
        __syncthreads();

        // prefetch next tile
        if (k0 + GBK < DD) {
            int kn = k0 + GBK;
#pragma unroll
            for (int q = 0; q < 4; q++) {
                int i = tid + q * 256; int r = i >> 3; int c = i & 7;
                pa[q] = *(const float4*)&A[(size_t)(rowBase + r) * DD + kn + c * 4];
            }
#pragma unroll
            for (int q = 0; q < 2; q++) {
                int i = tid + q * 256; int r = i >> 4; int c = i & 15;
                pb[q] = *(const float4*)&W[(size_t)(kn + r) * DD + cb + c * 4];
            }
        }

        // compute
#pragma unroll
        for (int kk = 0; kk < GBK / 8; kk++) {
            int kb = kk * 8;
            uint32_t af[2][4], bf[4][2];
#pragma unroll
            for (int i = 0; i < 2; i++) {
                int m0 = warpM * 32 + i * 16;
                af[i][0] = __float_as_uint(sA[m0 + g][kb + t4]);
                af[i][1] = __float_as_uint(sA[m0 + g + 8][kb + t4]);
                af[i][2] = __float_as_uint(sA[m0 + g][kb + t4 + 4]);
                af[i][3] = __float_as_uint(sA[m0 + g + 8][kb + t4 + 4]);
            }
#pragma unroll
            for (int j = 0; j < 4; j++) {
                int n0 = warpN * 32 + j * 8 + g;
                bf[j][0] = __float_as_uint(sB[kb + t4][n0]);
                bf[j][1] = __float_as_uint(sB[kb + t4 + 4][n0]);
            }
#pragma unroll
            for (int i = 0; i < 2; i++)
#pragma unroll
                for (int j = 0; j < 4; j++)
                    mma_tf32(acc[i][j], af[i], bf[j]);
        }
        __syncthreads();
    }

    // epilogue: add bias, write
#pragma unroll
    for (int i = 0; i < 2; i++) {
        int r0 = rowBase + warpM * 32 + i * 16 + g;
#pragma unroll
        for (int j = 0; j < 4; j++) {
            int c0 = cb + warpN * 32 + j * 8 + t4 * 2;
            float b0 = bias[c0], b1 = bias[c0 + 1];
            Cout[(size_t)r0 * DD + c0]           = acc[i][j][0] + b0;
            Cout[(size_t)r0 * DD + c0 + 1]       = acc[i][j][1] + b1;
            Cout[(size_t)(r0 + 8) * DD + c0]     = acc[i][j][2] + b0;
            Cout[(size_t)(r0 + 8) * DD + c0 + 1] = acc[i][j][3] + b1;
        }
    }
}

// ============================================================
// 3) Edge scores + softmax + aggregation + gate logit.
//    One block (256 thr) per (b,l).
// ============================================================
__global__ __launch_bounds__(256) void edge_kernel(
    const float* __restrict__ attn, const float* __restrict__ hidden,
    const float* __restrict__ attn_vec, const float* __restrict__ gat_bias,
    const float* __restrict__ gate_W, const float* __restrict__ gate_b) {
    __shared__ float fdst[DD];
    __shared__ float av[DD];
    __shared__ float wk[KSEL];
    __shared__ int   ik[KSEL];
    __shared__ float red[256];

    int row = blockIdx.x;
    int b = row / LL;
    int t = threadIdx.x;

    for (int d = t; d < DD; d += 256) {
        fdst[d] = g_fdst[(size_t)row * DD + d];
        av[d]   = attn_vec[d];
    }
    if (t < KSEL) ik[t] = g_idx[row * KSEL + t];
    __syncthreads();

    int warp = t >> 5, lane = t & 31;
    for (int k = warp; k < KSEL; k += 8) {
        int idxk = ik[k];
        const float* fs = &g_fsrc[(size_t)(b * LL + idxk) * DD];
        float sum = 0.f;
#pragma unroll 4
        for (int d = lane; d < DD; d += 32) {
            float x = fs[d] + fdst[d];
            x = x > 0.f ? x : 0.2f * x;
            sum += x * av[d];
        }
#pragma unroll
        for (int o = 16; o > 0; o >>= 1) sum += __shfl_xor_sync(0xffffffffu, sum, o);
        if (lane == 0) {
            float val = attn[(size_t)row * LL + idxk];
            wk[k] = (val > 0.f) ? sum : -1e9f;
        }
    }
    __syncthreads();

    float m = -1e30f;
    for (int k = 0; k < KSEL; k++) m = fmaxf(m, wk[k]);
    __syncthreads();
    if (t < KSEL) wk[t] = expf(wk[t] - m);
    __syncthreads();
    float Z = 0.f;
    for (int k = 0; k < KSEL; k++) Z += wk[k];
    float invZ = 1.f / Z;

    float a0 = 0.f, a1 = 0.f, a2 = 0.f;
    for (int k = 0; k < KSEL; k++) {
        const float* fs = &g_fsrc[(size_t)(b * LL + ik[k]) * DD];
        float w = wk[k] * invZ;
        a0 += w * fs[t];
        a1 += w * fs[t + 256];
        a2 += w * fs[t + 512];
    }

    float accv[3] = {a0, a1, a2};
    float gp = 0.f;
#pragma unroll
    for (int q = 0; q < 3; q++) {
        int d = t + q * 256;
        float x = accv[q] + hidden[(size_t)row * DD + d] + gat_bias[d];
        x = x > 0.f ? x : 0.01f * x;
        g_h[(size_t)row * DD + d] = x;
        gp += x * gate_W[d];
    }
    red[t] = gp;
    __syncthreads();
#pragma unroll
    for (int s = 128; s > 0; s >>= 1) {
        if (t < s) red[t] += red[t + s];
        __syncthreads();
    }
    if (t == 0) g_gate[row] = red[0] + gate_b[0];
}

// ============================================================
// 4) Gate softmax over L per batch. One block (512) per batch.
// ============================================================
__global__ void gatesm_kernel() {
    __shared__ float red[512];
    int b = blockIdx.x, t = threadIdx.x;
    float v = g_gate[b * LL + t];
    red[t] = v;
    __syncthreads();
#pragma unroll
    for (int s = 256; s > 0; s >>= 1) {
        if (t < s) red[t] = fmaxf(red[t], red[t + s]);
        __syncthreads();
    }
    float m = red[0];
    __syncthreads();
    float e = expf(v - m);
    red[t] = e;
    __syncthreads();
#pragma unroll
    for (int s = 256; s > 0; s >>= 1) {
        if (t < s) red[t] += red[t + s];
        __syncthreads();
    }
    float Z = red[0];
    g_gate[b * LL + t] = e / Z;
}

// ============================================================
// 5) Partial weighted pooling: grid (NSPLIT, B), 256 thr.
// ============================================================
__global__ void pool_kernel() {
    int b = blockIdx.y, s = blockIdx.x, t = threadIdx.x;
    float a0 = 0.f, a1 = 0.f, a2 = 0.f;
    int l0 = s * (LL / NSPLIT);
    for (int l = l0; l < l0 + (LL / NSPLIT); l++) {
        float p = g_gate[b * LL + l];
        const float* hr = &g_h[(size_t)(b * LL + l) * DD];
        a0 += p * hr[t];
        a1 += p * hr[t + 256];
        a2 += p * hr[t + 512];
    }
    float* o = &g_part[(size_t)(b * NSPLIT + s) * DD];
    o[t] = a0; o[t + 256] = a1; o[t + 512] = a2;
}

// ============================================================
// 6) Head: finish pool, relu, LN, FC(768->384), LN2. One block/batch.
// ============================================================
__device__ __forceinline__ float bsum(float v, float* red, int t, int n) {
    red[t] = v;
    __syncthreads();
#pragma unroll
    for (int s = 256; s > 0; s >>= 1) {
        if (t < s && t + s < n) red[t] += red[t + s];
        __syncthreads();
    }
    float r = red[0];
    __syncthreads();
    return r;
}

__global__ __launch_bounds__(DOUT) void head_kernel(
    const float* __restrict__ ln_g, const float* __restrict__ ln_b,
    const float* __restrict__ fc_W, const float* __restrict__ fc_b,
    const float* __restrict__ ln2_g, const float* __restrict__ ln2_b,
    float* __restrict__ out) {
    __shared__ float xn[DD];
    __shared__ float red[DOUT];
    int b = blockIdx.x, t = threadIdx.x;

    float x0 = 0.f, x1 = 0.f;
    for (int s = 0; s < NSPLIT; s++) {
        const float* pp = &g_part[(size_t)(b * NSPLIT + s) * DD];
        x0 += pp[t];
        x1 += pp[t + DOUT];
    }
    x0 = fmaxf(x0, 0.f);
    x1 = fmaxf(x1, 0.f);

    float mu  = bsum(x0 + x1, red, t, DOUT) * (1.f / DD);
    float q   = bsum(x0 * x0 + x1 * x1, red, t, DOUT) * (1.f / DD);
    float var = q - mu * mu;
    float rstd = rsqrtf(var + 1e-5f);
    xn[t]        = (x0 - mu) * rstd * ln_g[t] + ln_b[t];
    xn[t + DOUT] = (x1 - mu) * rstd * ln_g[t + DOUT] + ln_b[t + DOUT];
    __syncthreads();

    float o = fc_b[t];
#pragma unroll 4
    for (int d = 0; d < DD; d++) o += xn[d] * fc_W[d * DOUT + t];

    float mu2  = bsum(o, red, t, DOUT) * (1.f / DOUT);
    float q2   = bsum(o * o, red, t, DOUT) * (1.f / DOUT);
    float var2 = q2 - mu2 * mu2;
    out[b * DOUT + t] = (o - mu2) * rsqrtf(var2 + 1e-5f) * ln2_g[t] + ln2_b[t];
}

// ============================================================
extern "C" void kernel_launch(void* const* d_in, const int* in_sizes, int n_in,
                              void* d_out, int out_size) {
    const float* hidden = (const float*)d_in[0];
    const float* attn   = (const float*)d_in[1];
    const float* Wsrc   = (const float*)d_in[2];
    const float* bsrc   = (const float*)d_in[3];
    const float* Wdst   = (const float*)d_in[4];
    const float* bdst   = (const float*)d_in[5];
    const float* av     = (const float*)d_in[6];
    const float* gb     = (const float*)d_in[7];
    const float* gateW  = (const float*)d_in[8];
    const float* gateb  = (const float*)d_in[9];
    const float* lng    = (const float*)d_in[10];
    const float* lnb    = (const float*)d_in[11];
    const float* fcW    = (const float*)d_in[12];
    const float* fcb    = (const float*)d_in[13];
    const float* ln2g   = (const float*)d_in[14];
    const float* ln2b   = (const float*)d_in[15];
    float* out = (float*)d_out;

    topk_kernel<<<NROW, 512>>>(attn);
    gemm_tf32_kernel<<<dim3(24, 16), 256>>>(hidden, Wsrc, bsrc, Wdst, bdst);
    edge_kernel<<<NROW, 256>>>(attn, hidden, av, gb, gateW, gateb);
    gatesm_kernel<<<BB, 512>>>();
    pool_kernel<<<dim3(NSPLIT, BB), 256>>>();
    head_kernel<<<BB, DOUT>>>(lng, lnb, fcW, fcb, ln2g, ln2b, out);
}